// round 14
// baseline (speedup 1.0000x reference)
#include <cuda_runtime.h>
#include <cuda_fp16.h>
#include <cstdint>
#include <math.h>

#define SEQ   2048
#define EMB   4096
#define KVD   1024
#define NH    32
#define HD    128
#define NZ    2            // split-KV factor

// -------- scratch (device globals; no allocation allowed) --------
__device__ __half g_xh[SEQ * EMB];
__device__ __half g_qwh[EMB * EMB];
__device__ __half g_kwh[KVD * EMB];
__device__ __half g_vwh[KVD * EMB];
__device__ __half g_owh[EMB * EMB];

__device__ __half g_qh[SEQ * EMB];          // scaled Q
__device__ __half g_kh[SEQ * KVD];
__device__ __half g_vh[SEQ * KVD];
__device__ __half g_ah[SEQ * EMB];          // attention out

// split-KV attention partials (fp16 O, fp32 m/l)
__device__ __half g_poh[NZ * SEQ * EMB];
__device__ float  g_pm[NZ * NH * SEQ];
__device__ float  g_pl[NZ * NH * SEQ];

// ============================================================================
// helpers
// ============================================================================
__device__ __forceinline__ uint32_t smaddr(const void* p)
{
    return (uint32_t)__cvta_generic_to_shared(p);
}

__device__ __forceinline__ void cp16(uint32_t dst, const void* src)
{
    asm volatile("cp.async.cg.shared.global [%0], [%1], 16;"
                 :: "r"(dst), "l"(src));
}

__device__ __forceinline__ void cp_commit()
{
    asm volatile("cp.async.commit_group;");
}

template <int N>
__device__ __forceinline__ void cp_wait()
{
    asm volatile("cp.async.wait_group %0;" :: "n"(N));
}

__device__ __forceinline__ void ldsm_x4(uint32_t* r, const __half* p)
{
    uint32_t addr = smaddr(p);
    asm volatile("ldmatrix.sync.aligned.m8n8.x4.shared.b16 {%0,%1,%2,%3}, [%4];"
                 : "=r"(r[0]), "=r"(r[1]), "=r"(r[2]), "=r"(r[3])
                 : "r"(addr));
}

__device__ __forceinline__ void ldsm_x4t(uint32_t* r, const __half* p)
{
    uint32_t addr = smaddr(p);
    asm volatile("ldmatrix.sync.aligned.m8n8.x4.trans.shared.b16 {%0,%1,%2,%3}, [%4];"
                 : "=r"(r[0]), "=r"(r[1]), "=r"(r[2]), "=r"(r[3])
                 : "r"(addr));
}

__device__ __forceinline__ void mma16816(float* c, const uint32_t* a,
                                         uint32_t b0, uint32_t b1)
{
    asm volatile(
        "mma.sync.aligned.m16n8k16.row.col.f32.f16.f16.f32 "
        "{%0,%1,%2,%3}, {%4,%5,%6,%7}, {%8,%9}, {%0,%1,%2,%3};"
        : "+f"(c[0]), "+f"(c[1]), "+f"(c[2]), "+f"(c[3])
        : "r"(a[0]), "r"(a[1]), "r"(a[2]), "r"(a[3]), "r"(b0), "r"(b1));
}

__device__ __forceinline__ uint32_t pack_h(float a, float b)
{
    __half2 t = __halves2half2(__float2half_rn(a), __float2half_rn(b));
    return *(uint32_t*)&t;
}

// ============================================================================
// merged fp32 -> fp16 conversion; 4 consecutive float4s per thread (MLP=4).
// float4 region bounds: x 2097152 | qw 6291456 | kw 7340032 | vw 8388608 |
// ow 12582912.  grid*256*4 = 12582912.
// ============================================================================
__global__ __launch_bounds__(256)
void cvt_all(const float4* __restrict__ x,  const float4* __restrict__ qw,
             const float4* __restrict__ kw, const float4* __restrict__ vw,
             const float4* __restrict__ ow,
             uint32_t* xh, uint32_t* qwh, uint32_t* kwh, uint32_t* vwh,
             uint32_t* owh)
{
    int base = (blockIdx.x * blockDim.x + threadIdx.x) * 4;
    const float4* src;
    uint32_t* dst;
    int off;
    if (base < 2097152) {
        src = x;  dst = xh;  off = 0;
    } else if (base < 6291456) {
        src = qw; dst = qwh; off = 2097152;
    } else if (base < 7340032) {
        src = kw; dst = kwh; off = 6291456;
    } else if (base < 8388608) {
        src = vw; dst = vwh; off = 7340032;
    } else {
        src = ow; dst = owh; off = 8388608;
    }
    int i = base - off;
    float4 v0 = src[i];
    float4 v1 = src[i + 1];
    float4 v2 = src[i + 2];
    float4 v3 = src[i + 3];
    uint4 r0;
    uint4 r1;
    r0.x = pack_h(v0.x, v0.y);
    r0.y = pack_h(v0.z, v0.w);
    r0.z = pack_h(v1.x, v1.y);
    r0.w = pack_h(v1.z, v1.w);
    r1.x = pack_h(v2.x, v2.y);
    r1.y = pack_h(v2.z, v2.w);
    r1.z = pack_h(v3.x, v3.y);
    r1.w = pack_h(v3.z, v3.w);
    *(uint4*)(dst + i * 2)     = r0;
    *(uint4*)(dst + i * 2 + 4) = r1;
}

// ============================================================================
// fp16 single-pass GEMM (NT): C = A @ B^T + bias (fp32 accum).
// 3-stage cp.async pipeline. Block tile 128x128x32, 256 threads, warp 64x32.
// Output: Ch -> fp16 (scaled by oscale); else fp32 C.
// ============================================================================
#define BKP 40
#define GSTG (2 * 128 * BKP)
#define GEMM_SMEM_BYTES (3 * GSTG * 2)   // 61440

__device__ __forceinline__
void gemm_body(const __half* __restrict__ Ahg,
               const __half* __restrict__ Bhg,
               const float* __restrict__ bias,
               float* __restrict__ C,
               __half* __restrict__ Ch,
               float oscale, int N, int K, int row0, int col0)
{
    extern __shared__ __half smg[];

    const int tid  = threadIdx.x;
    const int warp = tid >> 5;
    const int lane = tid & 31;
    const int wm = (warp >> 2) * 64;
    const int wn = (warp & 3) * 32;

    const int lr = tid >> 1;
    const int lc = (tid & 1) * 16;

    const __half* pAh = Ahg + (size_t)(row0 + lr) * K + lc;
    const __half* pBh = Bhg + (size_t)(col0 + lr) * K + lc;

    const int dstoff = lr * BKP + lc;

    float acc[4][4][4];
#pragma unroll
    for (int i = 0; i < 4; i++)
#pragma unroll
        for (int j = 0; j < 4; j++)
#pragma unroll
            for (int r = 0; r < 4; r++)
                acc[i][j][r] = 0.0f;

    const int lrow = lane & 15;
    const int lcol = (lane >> 4) * 8;

#define GPREFETCH(st, k0)                                                     \
    do {                                                                      \
        __half* sb = smg + (st) * GSTG + dstoff;                              \
        uint32_t d0 = smaddr(sb);                                             \
        cp16(d0,                      pAh + (k0));                            \
        cp16(d0 + 16,                 pAh + (k0) + 8);                        \
        cp16(d0 + 128 * BKP * 2,      pBh + (k0));                            \
        cp16(d0 + 128 * BKP * 2 + 16, pBh + (k0) + 8);                        \
    } while (0)

    GPREFETCH(0, 0);
    cp_commit();
    GPREFETCH(1, 32);
    cp_commit();

    int st = 0;
    for (int k0 = 0; k0 < K; k0 += 32) {
        if (k0 + 32 < K) cp_wait<1>(); else cp_wait<0>();
        __syncthreads();
        if (k0 + 64 < K) {
            int st2 = st + 2;
            if (st2 >= 3) st2 -= 3;
            GPREFETCH(st2, k0 + 64);
            cp_commit();
        }

        const __half* Ah = smg + st * GSTG;
        const __half* Bh = Ah + 128 * BKP;

#pragma unroll
        for (int ks = 0; ks < 2; ks++) {
            const int kk = ks * 16;
            uint32_t ah[4][4];
            uint32_t bh[2][4];
#pragma unroll
            for (int mi = 0; mi < 4; mi++) {
                ldsm_x4(ah[mi], Ah + (wm + mi * 16 + lrow) * BKP + kk + lcol);
            }
#pragma unroll
            for (int nb = 0; nb < 2; nb++) {
                ldsm_x4(bh[nb], Bh + (wn + nb * 16 + lrow) * BKP + kk + lcol);
            }
#pragma unroll
            for (int mi = 0; mi < 4; mi++) {
#pragma unroll
                for (int nj = 0; nj < 4; nj++) {
                    const int nb = nj >> 1;
                    const int ns = nj & 1;
                    mma16816(acc[mi][nj], ah[mi], bh[nb][ns], bh[nb][ns + 2]);
                }
            }
        }
        st = st + 1;
        if (st == 3) st = 0;
    }

#pragma unroll
    for (int mi = 0; mi < 4; mi++) {
#pragma unroll
        for (int nj = 0; nj < 4; nj++) {
            int row = row0 + wm + mi * 16 + (lane >> 2);
            int col = col0 + wn + nj * 8 + (lane & 3) * 2;
            float b0 = bias[col];
            float b1 = bias[col + 1];
            float v00 = acc[mi][nj][0] + b0;
            float v01 = acc[mi][nj][1] + b1;
            float v10 = acc[mi][nj][2] + b0;
            float v11 = acc[mi][nj][3] + b1;
            if (Ch) {
                *(uint32_t*)(Ch + (size_t)row * N + col) =
                    pack_h(v00 * oscale, v01 * oscale);
                *(uint32_t*)(Ch + (size_t)(row + 8) * N + col) =
                    pack_h(v10 * oscale, v11 * oscale);
            } else {
                float2 r0;
                float2 r1;
                r0.x = v00; r0.y = v01;
                r1.x = v10; r1.y = v11;
                *(float2*)(C + (size_t)row * N + col) = r0;
                *(float2*)(C + (size_t)(row + 8) * N + col) = r1;
            }
        }
    }
}

// merged Q/K/V projection: grid.x in [0,48): 0-31 Q tiles, 32-39 K, 40-47 V
__global__ __launch_bounds__(256, 2)
void gemm_qkv(const __half* __restrict__ xh,
              const __half* __restrict__ qwh,
              const __half* __restrict__ kwh,
              const __half* __restrict__ vwh,
              const float* __restrict__ q_b,
              const float* __restrict__ k_b,
              const float* __restrict__ v_b,
              __half* __restrict__ qh,
              __half* __restrict__ kh,
              __half* __restrict__ vh,
              float qscale)
{
    const int bx = blockIdx.x;
    const int row0 = blockIdx.y * 128;

    if (bx < 32) {
        gemm_body(xh, qwh, q_b, (float*)0, qh, qscale, EMB, EMB, row0, bx * 128);
    } else if (bx < 40) {
        gemm_body(xh, kwh, k_b, (float*)0, kh, 1.0f, KVD, EMB, row0,
                  (bx - 32) * 128);
    } else {
        gemm_body(xh, vwh, v_b, (float*)0, vh, 1.0f, KVD, EMB, row0,
                  (bx - 40) * 128);
    }
}

// O projection (fp32 out)
__global__ __launch_bounds__(256, 2)
void gemm_oproj(const __half* __restrict__ ah,
                const __half* __restrict__ owh,
                const float* __restrict__ o_b,
                float* __restrict__ out)
{
    gemm_body(ah, owh, o_b, out, (__half*)0, 1.0f, EMB, EMB,
              blockIdx.y * 128, blockIdx.x * 128);
}

// ============================================================================
// Split-KV flash attention (mma.sync fp16 single-pass), base-2 softermax.
// 64-query tiles, 128-thread CTAs (4 warps x 16 rows) to kill wave
// quantization: grid (32, 32, 2) = 2048 CTAs vs 296 slots -> 6.92 waves.
// Q persistent in smem; fp16 partial O. 2 CTAs/SM.
// ============================================================================
#define QROWS 64
#define KVP 136
#define QBYTES (QROWS * KVP * 2)           // persistent Q region: 17408
#define FSTG (2 * 64 * KVP)                // K + V per stage (halves)
#define FL_SMEM_BYTES (QBYTES + 2 * FSTG * 2)   // 87040
#define KT_PER_Z (SEQ / 64 / NZ)           // 16
#define FTHREADS 128

__global__ __launch_bounds__(FTHREADS, 2)
void flash_mma()
{
    extern __shared__ __half smf[];
    __half* Qs = smf;                       // persistent [QROWS][KVP]
    __half* KV = smf + QROWS * KVP;         // 2 stages of K|V

    const int tid  = threadIdx.x;
    const int warp = tid >> 5;              // 0..3
    const int lane = tid & 31;
    const int lrow = lane & 15;
    const int lcol = (lane >> 4) * 8;
    const int wq   = warp * 16;             // q-row within 64-row tile

    const int h   = blockIdx.y;
    const int hk  = h >> 2;
    const int q0  = blockIdx.x * QROWS;
    const int z   = blockIdx.z;
    const int kt0 = z * KT_PER_Z;

    // stage Q via cp.async (QROWS*16 quads / 128 threads = 8 iters)
#pragma unroll
    for (int it = 0; it < 8; it++) {
        int idx = tid + it * FTHREADS;
        int r = idx >> 4;
        int c = (idx & 15) * 8;
        size_t g = (size_t)(q0 + r) * EMB + h * HD + c;
        cp16(smaddr(Qs + r * KVP + c), g_qh + g);
    }

#define FPREFETCH(st, kt)                                                     \
    do {                                                                      \
        __half* sb = KV + (st) * FSTG;                                        \
        _Pragma("unroll")                                                     \
        for (int it = 0; it < 8; it++) {                                      \
            int idx = tid + it * FTHREADS;                                    \
            int r = idx >> 4;                                                 \
            int c = (idx & 15) * 8;                                           \
            size_t g = (size_t)((kt) * 64 + r) * KVD + hk * HD + c;           \
            uint32_t d0 = smaddr(sb + r * KVP + c);                           \
            cp16(d0,                g_kh + g);                                \
            cp16(d0 + 64 * KVP * 2, g_vh + g);                                \
        }                                                                     \
    } while (0)

    FPREFETCH(0, kt0);
    cp_commit();   // one group: Q + stage-0 KV

    float o[16][4];
#pragma unroll
    for (int i = 0; i < 16; i++)
#pragma unroll
        for (int r = 0; r < 4; r++)
            o[i][r] = 0.0f;

    float m1 = -1e30f;
    float m2 = -1e30f;
    float l1 = 0.0f;
    float l2 = 0.0f;

    int st = 0;
    for (int kt = kt0; kt < kt0 + KT_PER_Z; kt++) {
        cp_wait<0>();
        __syncthreads();
        if (kt + 1 < kt0 + KT_PER_Z) {
            FPREFETCH(st ^ 1, kt + 1);
            cp_commit();
        }

        const __half* Kh = KV + st * FSTG;
        const __half* Vh = Kh + 64 * KVP;

        // ---- S = Q K^T ----
        float s[8][4];
#pragma unroll
        for (int t = 0; t < 8; t++)
#pragma unroll
            for (int r = 0; r < 4; r++)
                s[t][r] = 0.0f;

#pragma unroll
        for (int ks = 0; ks < 8; ks++) {
            uint32_t qf[4];
            ldsm_x4(qf, Qs + (wq + lrow) * KVP + ks * 16 + lcol);
#pragma unroll
            for (int nsl = 0; nsl < 4; nsl++) {
                uint32_t kf[4];
                ldsm_x4(kf, Kh + (nsl * 16 + lrow) * KVP + ks * 16 + lcol);
                mma16816(s[nsl * 2],     qf, kf[0], kf[2]);
                mma16816(s[nsl * 2 + 1], qf, kf[1], kf[3]);
            }
        }

        // ---- online base-2 softmax ----
        float mx1 = -1e30f;
        float mx2 = -1e30f;
#pragma unroll
        for (int t = 0; t < 8; t++) {
            mx1 = fmaxf(mx1, fmaxf(s[t][0], s[t][1]));
            mx2 = fmaxf(mx2, fmaxf(s[t][2], s[t][3]));
        }
        mx1 = fmaxf(mx1, __shfl_xor_sync(0xffffffffu, mx1, 1));
        mx1 = fmaxf(mx1, __shfl_xor_sync(0xffffffffu, mx1, 2));
        mx2 = fmaxf(mx2, __shfl_xor_sync(0xffffffffu, mx2, 1));
        mx2 = fmaxf(mx2, __shfl_xor_sync(0xffffffffu, mx2, 2));

        float newm1 = fmaxf(m1, mx1);
        float newm2 = fmaxf(m2, mx2);
        float corr1 = exp2f(m1 - newm1);
        float corr2 = exp2f(m2 - newm2);
        m1 = newm1;
        m2 = newm2;

        float ps1 = 0.0f;
        float ps2 = 0.0f;
#pragma unroll
        for (int t = 0; t < 8; t++) {
            s[t][0] = exp2f(s[t][0] - newm1);
            s[t][1] = exp2f(s[t][1] - newm1);
            s[t][2] = exp2f(s[t][2] - newm2);
            s[t][3] = exp2f(s[t][3] - newm2);
            ps1 += s[t][0] + s[t][1];
            ps2 += s[t][2] + s[t][3];
        }
        l1 = l1 * corr1 + ps1;
        l2 = l2 * corr2 + ps2;

#pragma unroll
        for (int i = 0; i < 16; i++) {
            o[i][0] *= corr1;
            o[i][1] *= corr1;
            o[i][2] *= corr2;
            o[i][3] *= corr2;
        }

        // ---- O += P V (V via ldmatrix.trans) ----
#pragma unroll
        for (int ks2 = 0; ks2 < 4; ks2++) {
            uint32_t ph[4];
            ph[0] = pack_h(s[2 * ks2][0],     s[2 * ks2][1]);
            ph[1] = pack_h(s[2 * ks2][2],     s[2 * ks2][3]);
            ph[2] = pack_h(s[2 * ks2 + 1][0], s[2 * ks2 + 1][1]);
            ph[3] = pack_h(s[2 * ks2 + 1][2], s[2 * ks2 + 1][3]);
#pragma unroll
            for (int dsl = 0; dsl < 8; dsl++) {
                uint32_t vf[4];
                ldsm_x4t(vf, Vh + (ks2 * 16 + lrow) * KVP + dsl * 16 + lcol);
                mma16816(o[dsl * 2],     ph, vf[0], vf[1]);
                mma16816(o[dsl * 2 + 1], ph, vf[2], vf[3]);
            }
        }
        st ^= 1;
    }

    // ---- write fp16 partials + (m, l) ----
    l1 += __shfl_xor_sync(0xffffffffu, l1, 1);
    l1 += __shfl_xor_sync(0xffffffffu, l1, 2);
    l2 += __shfl_xor_sync(0xffffffffu, l2, 1);
    l2 += __shfl_xor_sync(0xffffffffu, l2, 2);

    const int row1 = q0 + wq + (lane >> 2);
    const int row2 = row1 + 8;
    const size_t zo = (size_t)z * SEQ * EMB;

    if ((lane & 3) == 0) {
        int mo = z * NH * SEQ + h * SEQ;
        g_pm[mo + row1] = m1;
        g_pl[mo + row1] = l1;
        g_pm[mo + row2] = m2;
        g_pl[mo + row2] = l2;
    }

#pragma unroll
    for (int nt = 0; nt < 16; nt++) {
        int col = h * HD + nt * 8 + (lane & 3) * 2;
        *(uint32_t*)(g_poh + zo + (size_t)row1 * EMB + col) =
            pack_h(o[nt][0], o[nt][1]);
        *(uint32_t*)(g_poh + zo + (size_t)row2 * EMB + col) =
            pack_h(o[nt][2], o[nt][3]);
    }
}

// ============================================================================
// combine NZ KV slices -> fp16 attention output
// one thread = 4 consecutive cols; total SEQ*EMB/4 threads
// ============================================================================
__global__ __launch_bounds__(256)
void attn_combine()
{
    int idx = blockIdx.x * blockDim.x + threadIdx.x;   // < SEQ*EMB/4
    int row  = idx >> 10;          // EMB/4 = 1024 quads per row
    int qc   = idx & 1023;
    int col  = qc * 4;
    int head = col >> 7;

    float mz[NZ];
    float lz[NZ];
    float mm = -1e30f;
#pragma unroll
    for (int zz = 0; zz < NZ; zz++) {
        int mo = zz * NH * SEQ + head * SEQ + row;
        mz[zz] = g_pm[mo];
        lz[zz] = g_pl[mo];
        mm = fmaxf(mm, mz[zz]);
    }

    float wsum = 0.0f;
    float a0 = 0.0f;
    float a1 = 0.0f;
    float a2 = 0.0f;
    float a3 = 0.0f;
    size_t off = (size_t)row * EMB + col;
#pragma unroll
    for (int zz = 0; zz < NZ; zz++) {
        float w = exp2f(mz[zz] - mm);
        wsum += w * lz[zz];
        uint2 p = *(const uint2*)(g_poh + (size_t)zz * SEQ * EMB + off);
        __half2 p0 = *(__half2*)&p.x;
        __half2 p1 = *(__half2*)&p.y;
        a0 += w * __low2float(p0);
        a1 += w * __high2float(p0);
        a2 += w * __low2float(p1);
        a3 += w * __high2float(p1);
    }

    float inv = 1.0f / wsum;
    uint2 r;
    r.x = pack_h(a0 * inv, a1 * inv);
    r.y = pack_h(a2 * inv, a3 * inv);
    *(uint2*)(g_ah + off) = r;
}

// ============================================================================
// launch
// ============================================================================
extern "C" void kernel_launch(void* const* d_in, const int* in_sizes, int n_in,
                              void* d_out, int out_size)
{
    const float* x   = (const float*)d_in[0];
    const float* q_w = (const float*)d_in[1];
    const float* q_b = (const float*)d_in[2];
    const float* k_w = (const float*)d_in[3];
    const float* k_b = (const float*)d_in[4];
    const float* v_w = (const float*)d_in[5];
    const float* v_b = (const float*)d_in[6];
    const float* o_w = (const float*)d_in[7];
    const float* o_b = (const float*)d_in[8];
    float* out = (float*)d_out;

    __half* xh = 0;
    __half* qwh = 0;
    __half* kwh = 0;
    __half* vwh = 0;
    __half* owh = 0;
    __half* qh = 0;
    __half* kh = 0;
    __half* vh = 0;
    __half* ah = 0;
    cudaGetSymbolAddress((void**)&xh,  g_xh);
    cudaGetSymbolAddress((void**)&qwh, g_qwh);
    cudaGetSymbolAddress((void**)&kwh, g_kwh);
    cudaGetSymbolAddress((void**)&vwh, g_vwh);
    cudaGetSymbolAddress((void**)&owh, g_owh);
    cudaGetSymbolAddress((void**)&qh,  g_qh);
    cudaGetSymbolAddress((void**)&kh,  g_kh);
    cudaGetSymbolAddress((void**)&vh,  g_vh);
    cudaGetSymbolAddress((void**)&ah,  g_ah);

    cudaFuncSetAttribute(gemm_qkv,
                         cudaFuncAttributeMaxDynamicSharedMemorySize,
                         GEMM_SMEM_BYTES);
    cudaFuncSetAttribute(gemm_oproj,
                         cudaFuncAttributeMaxDynamicSharedMemorySize,
                         GEMM_SMEM_BYTES);
    cudaFuncSetAttribute(flash_mma,
                         cudaFuncAttributeMaxDynamicSharedMemorySize,
                         FL_SMEM_BYTES);

    const float qscale = 0.08838834764831845f;   // 1/sqrt(128)

    cvt_all<<<12288, 256>>>((const float4*)x, (const float4*)q_w,
                            (const float4*)k_w, (const float4*)v_w,
                            (const float4*)o_w,
                            (uint32_t*)xh, (uint32_t*)qwh, (uint32_t*)kwh,
                            (uint32_t*)vwh, (uint32_t*)owh);

    gemm_qkv<<<dim3(48, 16), 256, GEMM_SMEM_BYTES>>>(
        xh, qwh, kwh, vwh, q_b, k_b, v_b, qh, kh, vh, qscale);

    flash_mma<<<dim3(SEQ / QROWS, NH, NZ), FTHREADS, FL_SMEM_BYTES>>>();
    attn_combine<<<(SEQ * EMB / 4) / 256, 256>>>();

    gemm_oproj<<<dim3(32, 16), 256, GEMM_SMEM_BYTES>>>(ah, owh, o_b, out);
}

// round 15
// speedup vs baseline: 1.0216x; 1.0216x over previous
#include <cuda_runtime.h>
#include <cuda_fp16.h>
#include <cstdint>
#include <math.h>

#define SEQ   2048
#define EMB   4096
#define KVD   1024
#define NH    32
#define HD    128
#define NZ    2            // split-KV factor

// -------- scratch (device globals; no allocation allowed) --------
__device__ __half g_xh[SEQ * EMB];
__device__ __half g_qwh[EMB * EMB];
__device__ __half g_kwh[KVD * EMB];
__device__ __half g_vwh[KVD * EMB];
__device__ __half g_owh[EMB * EMB];

__device__ __half g_qh[SEQ * EMB];          // scaled Q
__device__ __half g_kh[SEQ * KVD];
__device__ __half g_vh[SEQ * KVD];
__device__ __half g_ah[SEQ * EMB];          // attention out

// split-KV attention partials (fp16 O, fp32 m/l)
__device__ __half g_poh[NZ * SEQ * EMB];
__device__ float  g_pm[NZ * NH * SEQ];
__device__ float  g_pl[NZ * NH * SEQ];

// ============================================================================
// helpers
// ============================================================================
__device__ __forceinline__ uint32_t smaddr(const void* p)
{
    return (uint32_t)__cvta_generic_to_shared(p);
}

__device__ __forceinline__ void cp16(uint32_t dst, const void* src)
{
    asm volatile("cp.async.cg.shared.global [%0], [%1], 16;"
                 :: "r"(dst), "l"(src));
}

__device__ __forceinline__ void cp_commit()
{
    asm volatile("cp.async.commit_group;");
}

template <int N>
__device__ __forceinline__ void cp_wait()
{
    asm volatile("cp.async.wait_group %0;" :: "n"(N));
}

__device__ __forceinline__ void ldsm_x4(uint32_t* r, const __half* p)
{
    uint32_t addr = smaddr(p);
    asm volatile("ldmatrix.sync.aligned.m8n8.x4.shared.b16 {%0,%1,%2,%3}, [%4];"
                 : "=r"(r[0]), "=r"(r[1]), "=r"(r[2]), "=r"(r[3])
                 : "r"(addr));
}

__device__ __forceinline__ void ldsm_x4t(uint32_t* r, const __half* p)
{
    uint32_t addr = smaddr(p);
    asm volatile("ldmatrix.sync.aligned.m8n8.x4.trans.shared.b16 {%0,%1,%2,%3}, [%4];"
                 : "=r"(r[0]), "=r"(r[1]), "=r"(r[2]), "=r"(r[3])
                 : "r"(addr));
}

__device__ __forceinline__ void mma16816(float* c, const uint32_t* a,
                                         uint32_t b0, uint32_t b1)
{
    asm volatile(
        "mma.sync.aligned.m16n8k16.row.col.f32.f16.f16.f32 "
        "{%0,%1,%2,%3}, {%4,%5,%6,%7}, {%8,%9}, {%0,%1,%2,%3};"
        : "+f"(c[0]), "+f"(c[1]), "+f"(c[2]), "+f"(c[3])
        : "r"(a[0]), "r"(a[1]), "r"(a[2]), "r"(a[3]), "r"(b0), "r"(b1));
}

__device__ __forceinline__ uint32_t pack_h(float a, float b)
{
    __half2 t = __halves2half2(__float2half_rn(a), __float2half_rn(b));
    return *(uint32_t*)&t;
}

// ============================================================================
// merged fp32 -> fp16 conversion; 4 consecutive float4s per thread (MLP=4).
// float4 region bounds: x 2097152 | qw 6291456 | kw 7340032 | vw 8388608 |
// ow 12582912.  grid*256*4 = 12582912.
// ============================================================================
__global__ __launch_bounds__(256)
void cvt_all(const float4* __restrict__ x,  const float4* __restrict__ qw,
             const float4* __restrict__ kw, const float4* __restrict__ vw,
             const float4* __restrict__ ow,
             uint32_t* xh, uint32_t* qwh, uint32_t* kwh, uint32_t* vwh,
             uint32_t* owh)
{
    int base = (blockIdx.x * blockDim.x + threadIdx.x) * 4;
    const float4* src;
    uint32_t* dst;
    int off;
    if (base < 2097152) {
        src = x;  dst = xh;  off = 0;
    } else if (base < 6291456) {
        src = qw; dst = qwh; off = 2097152;
    } else if (base < 7340032) {
        src = kw; dst = kwh; off = 6291456;
    } else if (base < 8388608) {
        src = vw; dst = vwh; off = 7340032;
    } else {
        src = ow; dst = owh; off = 8388608;
    }
    int i = base - off;
    float4 v0 = src[i];
    float4 v1 = src[i + 1];
    float4 v2 = src[i + 2];
    float4 v3 = src[i + 3];
    uint4 r0;
    uint4 r1;
    r0.x = pack_h(v0.x, v0.y);
    r0.y = pack_h(v0.z, v0.w);
    r0.z = pack_h(v1.x, v1.y);
    r0.w = pack_h(v1.z, v1.w);
    r1.x = pack_h(v2.x, v2.y);
    r1.y = pack_h(v2.z, v2.w);
    r1.z = pack_h(v3.x, v3.y);
    r1.w = pack_h(v3.z, v3.w);
    *(uint4*)(dst + i * 2)     = r0;
    *(uint4*)(dst + i * 2 + 4) = r1;
}

// ============================================================================
// fp16 single-pass GEMM (NT): C = A @ B^T + bias (fp32 accum).
// 4-stage cp.async pipeline. Block tile 128x128x32, 256 threads, warp 64x32.
// Output: Ch -> fp16 (scaled by oscale); else fp32 C.
// ============================================================================
#define BKP 40
#define GSTG (2 * 128 * BKP)
#define GEMM_SMEM_BYTES (4 * GSTG * 2)   // 81920

__device__ __forceinline__
void gemm_body(const __half* __restrict__ Ahg,
               const __half* __restrict__ Bhg,
               const float* __restrict__ bias,
               float* __restrict__ C,
               __half* __restrict__ Ch,
               float oscale, int N, int K, int row0, int col0)
{
    extern __shared__ __half smg[];

    const int tid  = threadIdx.x;
    const int warp = tid >> 5;
    const int lane = tid & 31;
    const int wm = (warp >> 2) * 64;
    const int wn = (warp & 3) * 32;

    const int lr = tid >> 1;
    const int lc = (tid & 1) * 16;

    const __half* pAh = Ahg + (size_t)(row0 + lr) * K + lc;
    const __half* pBh = Bhg + (size_t)(col0 + lr) * K + lc;

    const int dstoff = lr * BKP + lc;

    float acc[4][4][4];
#pragma unroll
    for (int i = 0; i < 4; i++)
#pragma unroll
        for (int j = 0; j < 4; j++)
#pragma unroll
            for (int r = 0; r < 4; r++)
                acc[i][j][r] = 0.0f;

    const int lrow = lane & 15;
    const int lcol = (lane >> 4) * 8;

#define GPREFETCH(st, k0)                                                     \
    do {                                                                      \
        __half* sb = smg + (st) * GSTG + dstoff;                              \
        uint32_t d0 = smaddr(sb);                                             \
        cp16(d0,                      pAh + (k0));                            \
        cp16(d0 + 16,                 pAh + (k0) + 8);                        \
        cp16(d0 + 128 * BKP * 2,      pBh + (k0));                            \
        cp16(d0 + 128 * BKP * 2 + 16, pBh + (k0) + 8);                        \
    } while (0)

    GPREFETCH(0, 0);
    cp_commit();
    GPREFETCH(1, 32);
    cp_commit();
    GPREFETCH(2, 64);
    cp_commit();

    int st = 0;
    for (int k0 = 0; k0 < K; k0 += 32) {
        // remaining committed groups cover stages k0, k0+32, k0+64 (when
        // present); wait so that stage k0 is definitely complete.
        if (k0 + 96 <= K) {
            cp_wait<2>();
        } else if (k0 + 64 <= K) {
            cp_wait<1>();
        } else {
            cp_wait<0>();
        }
        __syncthreads();
        if (k0 + 96 < K) {
            int st3 = st + 3;
            if (st3 >= 4) st3 -= 4;
            GPREFETCH(st3, k0 + 96);
            cp_commit();
        }

        const __half* Ah = smg + st * GSTG;
        const __half* Bh = Ah + 128 * BKP;

#pragma unroll
        for (int ks = 0; ks < 2; ks++) {
            const int kk = ks * 16;
            uint32_t ah[4][4];
            uint32_t bh[2][4];
#pragma unroll
            for (int mi = 0; mi < 4; mi++) {
                ldsm_x4(ah[mi], Ah + (wm + mi * 16 + lrow) * BKP + kk + lcol);
            }
#pragma unroll
            for (int nb = 0; nb < 2; nb++) {
                ldsm_x4(bh[nb], Bh + (wn + nb * 16 + lrow) * BKP + kk + lcol);
            }
#pragma unroll
            for (int mi = 0; mi < 4; mi++) {
#pragma unroll
                for (int nj = 0; nj < 4; nj++) {
                    const int nb = nj >> 1;
                    const int ns = nj & 1;
                    mma16816(acc[mi][nj], ah[mi], bh[nb][ns], bh[nb][ns + 2]);
                }
            }
        }
        st = st + 1;
        if (st == 4) st = 0;
    }

#pragma unroll
    for (int mi = 0; mi < 4; mi++) {
#pragma unroll
        for (int nj = 0; nj < 4; nj++) {
            int row = row0 + wm + mi * 16 + (lane >> 2);
            int col = col0 + wn + nj * 8 + (lane & 3) * 2;
            float b0 = bias[col];
            float b1 = bias[col + 1];
            float v00 = acc[mi][nj][0] + b0;
            float v01 = acc[mi][nj][1] + b1;
            float v10 = acc[mi][nj][2] + b0;
            float v11 = acc[mi][nj][3] + b1;
            if (Ch) {
                *(uint32_t*)(Ch + (size_t)row * N + col) =
                    pack_h(v00 * oscale, v01 * oscale);
                *(uint32_t*)(Ch + (size_t)(row + 8) * N + col) =
                    pack_h(v10 * oscale, v11 * oscale);
            } else {
                float2 r0;
                float2 r1;
                r0.x = v00; r0.y = v01;
                r1.x = v10; r1.y = v11;
                *(float2*)(C + (size_t)row * N + col) = r0;
                *(float2*)(C + (size_t)(row + 8) * N + col) = r1;
            }
        }
    }
}

// merged Q/K/V projection: grid.x in [0,48): 0-31 Q tiles, 32-39 K, 40-47 V
__global__ __launch_bounds__(256, 2)
void gemm_qkv(const __half* __restrict__ xh,
              const __half* __restrict__ qwh,
              const __half* __restrict__ kwh,
              const __half* __restrict__ vwh,
              const float* __restrict__ q_b,
              const float* __restrict__ k_b,
              const float* __restrict__ v_b,
              __half* __restrict__ qh,
              __half* __restrict__ kh,
              __half* __restrict__ vh,
              float qscale)
{
    const int bx = blockIdx.x;
    const int row0 = blockIdx.y * 128;

    if (bx < 32) {
        gemm_body(xh, qwh, q_b, (float*)0, qh, qscale, EMB, EMB, row0, bx * 128);
    } else if (bx < 40) {
        gemm_body(xh, kwh, k_b, (float*)0, kh, 1.0f, KVD, EMB, row0,
                  (bx - 32) * 128);
    } else {
        gemm_body(xh, vwh, v_b, (float*)0, vh, 1.0f, KVD, EMB, row0,
                  (bx - 40) * 128);
    }
}

// O projection (fp32 out)
__global__ __launch_bounds__(256, 2)
void gemm_oproj(const __half* __restrict__ ah,
                const __half* __restrict__ owh,
                const float* __restrict__ o_b,
                float* __restrict__ out)
{
    gemm_body(ah, owh, o_b, out, (__half*)0, 1.0f, EMB, EMB,
              blockIdx.y * 128, blockIdx.x * 128);
}

// ============================================================================
// Split-KV flash attention (mma.sync fp16 single-pass), base-2 softermax.
// Q persistent in smem; NZ=2 KV slices (16 tiles each); fp16 partial O.
// 2 CTAs/SM. Grid (16, 32, 2).
// ============================================================================
#define KVP 136
#define QBYTES (128 * KVP * 2)             // persistent Q region: 34816
#define FSTG (2 * 64 * KVP)                // K + V per stage (halves)
#define FL_SMEM_BYTES (QBYTES + 2 * FSTG * 2)   // 104448
#define KT_PER_Z (SEQ / 64 / NZ)           // 16

__global__ __launch_bounds__(256, 2)
void flash_mma()
{
    extern __shared__ __half smf[];
    __half* Qs = smf;                       // persistent [128][KVP]
    __half* KV = smf + 128 * KVP;           // 2 stages of K|V

    const int tid  = threadIdx.x;
    const int warp = tid >> 5;
    const int lane = tid & 31;
    const int lrow = lane & 15;
    const int lcol = (lane >> 4) * 8;
    const int wq   = warp * 16;

    const int h   = blockIdx.y;
    const int hk  = h >> 2;
    const int q0  = blockIdx.x * 128;
    const int z   = blockIdx.z;
    const int kt0 = z * KT_PER_Z;

    // stage Q via cp.async (8 quads per thread)
#pragma unroll
    for (int it = 0; it < 8; it++) {
        int idx = tid + it * 256;
        int r = idx >> 4;
        int c = (idx & 15) * 8;
        size_t g = (size_t)(q0 + r) * EMB + h * HD + c;
        cp16(smaddr(Qs + r * KVP + c), g_qh + g);
    }

#define FPREFETCH(st, kt)                                                     \
    do {                                                                      \
        __half* sb = KV + (st) * FSTG;                                        \
        _Pragma("unroll")                                                     \
        for (int it = 0; it < 4; it++) {                                      \
            int idx = tid + it * 256;                                         \
            int r = idx >> 4;                                                 \
            int c = (idx & 15) * 8;                                           \
            size_t g = (size_t)((kt) * 64 + r) * KVD + hk * HD + c;           \
            uint32_t d0 = smaddr(sb + r * KVP + c);                           \
            cp16(d0,                g_kh + g);                                \
            cp16(d0 + 64 * KVP * 2, g_vh + g);                                \
        }                                                                     \
    } while (0)

    FPREFETCH(0, kt0);
    cp_commit();   // one group: Q + stage-0 KV

    float o[16][4];
#pragma unroll
    for (int i = 0; i < 16; i++)
#pragma unroll
        for (int r = 0; r < 4; r++)
            o[i][r] = 0.0f;

    float m1 = -1e30f;
    float m2 = -1e30f;
    float l1 = 0.0f;
    float l2 = 0.0f;

    int st = 0;
    for (int kt = kt0; kt < kt0 + KT_PER_Z; kt++) {
        cp_wait<0>();
        __syncthreads();
        if (kt + 1 < kt0 + KT_PER_Z) {
            FPREFETCH(st ^ 1, kt + 1);
            cp_commit();
        }

        const __half* Kh = KV + st * FSTG;
        const __half* Vh = Kh + 64 * KVP;

        // ---- S = Q K^T ----
        float s[8][4];
#pragma unroll
        for (int t = 0; t < 8; t++)
#pragma unroll
            for (int r = 0; r < 4; r++)
                s[t][r] = 0.0f;

#pragma unroll
        for (int ks = 0; ks < 8; ks++) {
            uint32_t qf[4];
            ldsm_x4(qf, Qs + (wq + lrow) * KVP + ks * 16 + lcol);
#pragma unroll
            for (int nsl = 0; nsl < 4; nsl++) {
                uint32_t kf[4];
                ldsm_x4(kf, Kh + (nsl * 16 + lrow) * KVP + ks * 16 + lcol);
                mma16816(s[nsl * 2],     qf, kf[0], kf[2]);
                mma16816(s[nsl * 2 + 1], qf, kf[1], kf[3]);
            }
        }

        // ---- online base-2 softmax ----
        float mx1 = -1e30f;
        float mx2 = -1e30f;
#pragma unroll
        for (int t = 0; t < 8; t++) {
            mx1 = fmaxf(mx1, fmaxf(s[t][0], s[t][1]));
            mx2 = fmaxf(mx2, fmaxf(s[t][2], s[t][3]));
        }
        mx1 = fmaxf(mx1, __shfl_xor_sync(0xffffffffu, mx1, 1));
        mx1 = fmaxf(mx1, __shfl_xor_sync(0xffffffffu, mx1, 2));
        mx2 = fmaxf(mx2, __shfl_xor_sync(0xffffffffu, mx2, 1));
        mx2 = fmaxf(mx2, __shfl_xor_sync(0xffffffffu, mx2, 2));

        float newm1 = fmaxf(m1, mx1);
        float newm2 = fmaxf(m2, mx2);
        float corr1 = exp2f(m1 - newm1);
        float corr2 = exp2f(m2 - newm2);
        m1 = newm1;
        m2 = newm2;

        float ps1 = 0.0f;
        float ps2 = 0.0f;
#pragma unroll
        for (int t = 0; t < 8; t++) {
            s[t][0] = exp2f(s[t][0] - newm1);
            s[t][1] = exp2f(s[t][1] - newm1);
            s[t][2] = exp2f(s[t][2] - newm2);
            s[t][3] = exp2f(s[t][3] - newm2);
            ps1 += s[t][0] + s[t][1];
            ps2 += s[t][2] + s[t][3];
        }
        l1 = l1 * corr1 + ps1;
        l2 = l2 * corr2 + ps2;

#pragma unroll
        for (int i = 0; i < 16; i++) {
            o[i][0] *= corr1;
            o[i][1] *= corr1;
            o[i][2] *= corr2;
            o[i][3] *= corr2;
        }

        // ---- O += P V (V via ldmatrix.trans) ----
#pragma unroll
        for (int ks2 = 0; ks2 < 4; ks2++) {
            uint32_t ph[4];
            ph[0] = pack_h(s[2 * ks2][0],     s[2 * ks2][1]);
            ph[1] = pack_h(s[2 * ks2][2],     s[2 * ks2][3]);
            ph[2] = pack_h(s[2 * ks2 + 1][0], s[2 * ks2 + 1][1]);
            ph[3] = pack_h(s[2 * ks2 + 1][2], s[2 * ks2 + 1][3]);
#pragma unroll
            for (int dsl = 0; dsl < 8; dsl++) {
                uint32_t vf[4];
                ldsm_x4t(vf, Vh + (ks2 * 16 + lrow) * KVP + dsl * 16 + lcol);
                mma16816(o[dsl * 2],     ph, vf[0], vf[1]);
                mma16816(o[dsl * 2 + 1], ph, vf[2], vf[3]);
            }
        }
        st ^= 1;
    }

    // ---- write fp16 partials + (m, l) ----
    l1 += __shfl_xor_sync(0xffffffffu, l1, 1);
    l1 += __shfl_xor_sync(0xffffffffu, l1, 2);
    l2 += __shfl_xor_sync(0xffffffffu, l2, 1);
    l2 += __shfl_xor_sync(0xffffffffu, l2, 2);

    const int row1 = q0 + wq + (lane >> 2);
    const int row2 = row1 + 8;
    const size_t zo = (size_t)z * SEQ * EMB;

    if ((lane & 3) == 0) {
        int mo = z * NH * SEQ + h * SEQ;
        g_pm[mo + row1] = m1;
        g_pl[mo + row1] = l1;
        g_pm[mo + row2] = m2;
        g_pl[mo + row2] = l2;
    }

#pragma unroll
    for (int nt = 0; nt < 16; nt++) {
        int col = h * HD + nt * 8 + (lane & 3) * 2;
        *(uint32_t*)(g_poh + zo + (size_t)row1 * EMB + col) =
            pack_h(o[nt][0], o[nt][1]);
        *(uint32_t*)(g_poh + zo + (size_t)row2 * EMB + col) =
            pack_h(o[nt][2], o[nt][3]);
    }
}

// ============================================================================
// combine NZ KV slices -> fp16 attention output
// one thread = 4 consecutive cols; total SEQ*EMB/4 threads
// ============================================================================
__global__ __launch_bounds__(256)
void attn_combine()
{
    int idx = blockIdx.x * blockDim.x + threadIdx.x;   // < SEQ*EMB/4
    int row  = idx >> 10;          // EMB/4 = 1024 quads per row
    int qc   = idx & 1023;
    int col  = qc * 4;
    int head = col >> 7;

    float mz[NZ];
    float lz[NZ];
    float mm = -1e30f;
#pragma unroll
    for (int zz = 0; zz < NZ; zz++) {
        int mo = zz * NH * SEQ + head * SEQ + row;
        mz[zz] = g_pm[mo];
        lz[zz] = g_pl[mo];
        mm = fmaxf(mm, mz[zz]);
    }

    float wsum = 0.0f;
    float a0 = 0.0f;
    float a1 = 0.0f;
    float a2 = 0.0f;
    float a3 = 0.0f;
    size_t off = (size_t)row * EMB + col;
#pragma unroll
    for (int zz = 0; zz < NZ; zz++) {
        float w = exp2f(mz[zz] - mm);
        wsum += w * lz[zz];
        uint2 p = *(const uint2*)(g_poh + (size_t)zz * SEQ * EMB + off);
        __half2 p0 = *(__half2*)&p.x;
        __half2 p1 = *(__half2*)&p.y;
        a0 += w * __low2float(p0);
        a1 += w * __high2float(p0);
        a2 += w * __low2float(p1);
        a3 += w * __high2float(p1);
    }

    float inv = 1.0f / wsum;
    uint2 r;
    r.x = pack_h(a0 * inv, a1 * inv);
    r.y = pack_h(a2 * inv, a3 * inv);
    *(uint2*)(g_ah + off) = r;
}

// ============================================================================
// launch
// ============================================================================
extern "C" void kernel_launch(void* const* d_in, const int* in_sizes, int n_in,
                              void* d_out, int out_size)
{
    const float* x   = (const float*)d_in[0];
    const float* q_w = (const float*)d_in[1];
    const float* q_b = (const float*)d_in[2];
    const float* k_w = (const float*)d_in[3];
    const float* k_b = (const float*)d_in[4];
    const float* v_w = (const float*)d_in[5];
    const float* v_b = (const float*)d_in[6];
    const float* o_w = (const float*)d_in[7];
    const float* o_b = (const float*)d_in[8];
    float* out = (float*)d_out;

    __half* xh = 0;
    __half* qwh = 0;
    __half* kwh = 0;
    __half* vwh = 0;
    __half* owh = 0;
    __half* qh = 0;
    __half* kh = 0;
    __half* vh = 0;
    __half* ah = 0;
    cudaGetSymbolAddress((void**)&xh,  g_xh);
    cudaGetSymbolAddress((void**)&qwh, g_qwh);
    cudaGetSymbolAddress((void**)&kwh, g_kwh);
    cudaGetSymbolAddress((void**)&vwh, g_vwh);
    cudaGetSymbolAddress((void**)&owh, g_owh);
    cudaGetSymbolAddress((void**)&qh,  g_qh);
    cudaGetSymbolAddress((void**)&kh,  g_kh);
    cudaGetSymbolAddress((void**)&vh,  g_vh);
    cudaGetSymbolAddress((void**)&ah,  g_ah);

    cudaFuncSetAttribute(gemm_qkv,
                         cudaFuncAttributeMaxDynamicSharedMemorySize,
                         GEMM_SMEM_BYTES);
    cudaFuncSetAttribute(gemm_oproj,
                         cudaFuncAttributeMaxDynamicSharedMemorySize,
                         GEMM_SMEM_BYTES);
    cudaFuncSetAttribute(flash_mma,
                         cudaFuncAttributeMaxDynamicSharedMemorySize,
                         FL_SMEM_BYTES);

    const float qscale = 0.08838834764831845f;   // 1/sqrt(128)

    cvt_all<<<12288, 256>>>((const float4*)x, (const float4*)q_w,
                            (const float4*)k_w, (const float4*)v_w,
                            (const float4*)o_w,
                            (uint32_t*)xh, (uint32_t*)qwh, (uint32_t*)kwh,
                            (uint32_t*)vwh, (uint32_t*)owh);

    gemm_qkv<<<dim3(48, 16), 256, GEMM_SMEM_BYTES>>>(
        xh, qwh, kwh, vwh, q_b, k_b, v_b, qh, kh, vh, qscale);

    flash_mma<<<dim3(16, 32, NZ), 256, FL_SMEM_BYTES>>>();
    attn_combine<<<(SEQ * EMB / 4) / 256, 256>>>();

    gemm_oproj<<<dim3(32, 16), 256, GEMM_SMEM_BYTES>>>(ah, owh, o_b, out);
}